// round 4
// baseline (speedup 1.0000x reference)
#include <cuda_runtime.h>
#include <math.h>

#define NB 8
#define NG 512
#define NT 1024
#define NK 5
#define NC 3

#define TPB 256
#define WPB 8                    // warps per block (main)

// scratch (device globals — allocation-free per harness rules)
__device__ float4 d_xs[NB * NG];        // {r0*x0, r1*x1, r2*x2, 0}
__device__ float4 d_hs[NB * NG];        // {hsum0, hsum1, hsum2, 0}
__device__ float4 d_ts[NB * NT];        // {r0*t0, r1*t1, r2*t2, bias}
__device__ float  d_a2[NK * NC];        // -0.5*log2(e)/scale^2
__device__ int    d_uni;

__device__ __forceinline__ float ex2f(float x) {
    float y;
    asm("ex2.approx.ftz.f32 %0, %1;" : "=f"(y) : "f"(x));
    return y;
}

__device__ __forceinline__ float warp_sum(float v) {
    #pragma unroll
    for (int off = 16; off; off >>= 1)
        v += __shfl_xor_sync(0xffffffffu, v, off);
    return v;
}

// ---------------- prep: one item per thread, no loops ----------------
__global__ __launch_bounds__(TPB)
void prep_kernel(const float* __restrict__ x_grid,
                 const float* __restrict__ h_grid,
                 const float* __restrict__ target_x,
                 const float* __restrict__ sigma,
                 const float* __restrict__ g_w,
                 const float* __restrict__ g_b)
{
    const int gid = blockIdx.x * TPB + threadIdx.x;   // 0 .. 12287

    // coefficient set (tiny; every thread computes it)
    float a2[NK][NC];
    #pragma unroll
    for (int k = 0; k < NK; k++)
        #pragma unroll
        for (int c = 0; c < NC; c++) {
            float s   = __expf(sigma[k * NC + c]) + 1e-6f;
            float inv = 1.0f / s;
            a2[k][c]  = -0.5f * 1.4426950408889634f * inv * inv;
        }
    bool uni = true;
    #pragma unroll
    for (int k = 1; k < NK; k++)
        #pragma unroll
        for (int c = 0; c < NC; c++)
            uni = uni && (a2[k][c] == a2[0][c]);

    if (gid == 0) {
        d_uni = uni ? 1 : 0;
        #pragma unroll
        for (int k = 0; k < NK; k++)
            #pragma unroll
            for (int c = 0; c < NC; c++)
                d_a2[k * NC + c] = a2[k][c];
    }

    const float r0 = uni ? sqrtf(-a2[0][0]) : 1.0f;
    const float r1 = uni ? sqrtf(-a2[0][1]) : 1.0f;
    const float r2 = uni ? sqrtf(-a2[0][2]) : 1.0f;

    if (gid < NB * NG) {
        // per-(b,g): scaled coords + hsum
        const int i = gid;
        const float* xp = x_grid + i * NC;
        const float* hp = h_grid + i * NK * NC;
        float gw[NK];
        #pragma unroll
        for (int k = 0; k < NK; k++) gw[k] = g_w[k];
        float h0 = 0.f, h1 = 0.f, h2 = 0.f;
        #pragma unroll
        for (int k = 0; k < NK; k++) {
            h0 += gw[k] * hp[k * NC + 0];
            h1 += gw[k] * hp[k * NC + 1];
            h2 += gw[k] * hp[k * NC + 2];
        }
        d_xs[i] = make_float4(xp[0] * r0, xp[1] * r1, xp[2] * r2, 0.f);
        d_hs[i] = make_float4(h0, h1, h2, 0.f);
    } else {
        // per-(b,t): scaled target + bias
        const int i = gid - NB * NG;     // 0 .. 8191
        const float* tp = target_x + i * NC;
        d_ts[i] = make_float4(tp[0] * r0, tp[1] * r1, tp[2] * r2, g_b[0]);
    }
}

// ---------------- main: warp-per-target, lanes-over-g ----------------
__global__ __launch_bounds__(TPB)
void main_kernel(const float* __restrict__ x_grid,
                 const float* __restrict__ h_grid,
                 const float* __restrict__ g_w,
                 float* __restrict__ out)
{
    const int tid  = threadIdx.x;
    const int warp = tid >> 5;
    const int lane = tid & 31;
    const int b    = blockIdx.y;
    const int t    = blockIdx.x * WPB + warp;

    const float4 tv = d_ts[b * NT + t];   // {t0',t1',t2',bias}

    float acc0 = 0.f, acc1 = 0.f, acc2 = 0.f;

    if (d_uni) {
        const float4* xs = d_xs + b * NG;
        const float4* hs = d_hs + b * NG;
        #pragma unroll 4
        for (int i = 0; i < NG / 32; i++) {
            const int g = i * 32 + lane;
            const float4 xv = xs[g];
            const float4 hv = hs[g];
            float d;
            d = xv.x - tv.x; acc0 += hv.x * ex2f(d * (-d));
            d = xv.y - tv.y; acc1 += hv.y * ex2f(d * (-d));
            d = xv.z - tv.z; acc2 += hv.z * ex2f(d * (-d));
        }
    } else {
        // general path: per-(k,c) scales, raw inputs (targets are raw: r=1)
        float a2[NK][NC];
        #pragma unroll
        for (int k = 0; k < NK; k++)
            #pragma unroll
            for (int c = 0; c < NC; c++)
                a2[k][c] = d_a2[k * NC + c];
        float gw[NK];
        #pragma unroll
        for (int k = 0; k < NK; k++) gw[k] = __ldg(&g_w[k]);

        for (int i = 0; i < NG / 32; i++) {
            const int g = i * 32 + lane;
            const float* xp = x_grid + (b * NG + g) * NC;
            const float x0 = xp[0], x1 = xp[1], x2 = xp[2];
            const float u0 = (x0 - tv.x) * (x0 - tv.x);
            const float u1 = (x1 - tv.y) * (x1 - tv.y);
            const float u2 = (x2 - tv.z) * (x2 - tv.z);
            const float* hp = h_grid + (b * NG + g) * NK * NC;
            #pragma unroll
            for (int k = 0; k < NK; k++) {
                acc0 += gw[k] * hp[k * NC + 0] * ex2f(a2[k][0] * u0);
                acc1 += gw[k] * hp[k * NC + 1] * ex2f(a2[k][1] * u1);
                acc2 += gw[k] * hp[k * NC + 2] * ex2f(a2[k][2] * u2);
            }
        }
    }

    acc0 = warp_sum(acc0);
    acc1 = warp_sum(acc1);
    acc2 = warp_sum(acc2);

    if (lane == 0) {
        float* o = out + (b * NT + t) * NC;
        o[0] = acc0 + tv.w;
        o[1] = acc1 + tv.w;
        o[2] = acc2 + tv.w;
    }
}

extern "C" void kernel_launch(void* const* d_in, const int* in_sizes, int n_in,
                              void* d_out, int out_size)
{
    const float* x_grid   = (const float*)d_in[0];  // (8, 512, 3)
    const float* h_grid   = (const float*)d_in[1];  // (8, 512, 5, 3)
    const float* target_x = (const float*)d_in[2];  // (8, 1024, 3)
    const float* sigma    = (const float*)d_in[3];  // (5, 3)
    const float* g_w      = (const float*)d_in[4];  // (1, 5)
    const float* g_b      = (const float*)d_in[5];  // (1,)
    float* out = (float*)d_out;                     // (8, 1024, 3)

    // 48 blocks * 256 threads = 12288 = NB*NG (4096) + NB*NT (8192) items
    prep_kernel<<<48, TPB>>>(x_grid, h_grid, target_x, sigma, g_w, g_b);

    dim3 grid(NT / WPB, NB);   // 128 x 8 = 1024 blocks, warp per target
    main_kernel<<<grid, TPB>>>(x_grid, h_grid, g_w, out);
}

// round 6
// speedup vs baseline: 1.1918x; 1.1918x over previous
#include <cuda_runtime.h>
#include <math.h>

#define NB 8
#define NG 512
#define NT 1024
#define NK 5
#define NC 3

#define TPB 256
#define WPB 8
#define TGT_PER_WARP 4
#define T_PER_BLOCK (WPB * TGT_PER_WARP)   // 32 targets per block

__device__ __forceinline__ float ex2f(float x) {
    float y;
    asm("ex2.approx.ftz.f32 %0, %1;" : "=f"(y) : "f"(x));
    return y;
}

__device__ __forceinline__ float warp_sum(float v) {
    #pragma unroll
    for (int off = 16; off; off >>= 1)
        v += __shfl_xor_sync(0xffffffffu, v, off);
    return v;
}

__global__ __launch_bounds__(TPB)
void fused_kernel(const float* __restrict__ x_grid,
                  const float* __restrict__ h_grid,
                  const float* __restrict__ target_x,
                  const float* __restrict__ sigma,
                  const float* __restrict__ g_w,
                  const float* __restrict__ g_b,
                  float* __restrict__ out)
{
    // union buffer: fast path = 2 x float4[NG] (16KB); general = 18 rows x NG (36KB)
    __shared__ __align__(16) float smem_buf[(NC + NK * NC) * NG];
    float4* sxs = (float4*)smem_buf;          // [NG] scaled coords
    float4* shs = ((float4*)smem_buf) + NG;   // [NG] hsum

    const int tid  = threadIdx.x;
    const int warp = tid >> 5;
    const int lane = tid & 31;
    const int b    = blockIdx.y;

    // ---- coefficients (tiny, every thread) ----
    float a2[NK][NC];
    #pragma unroll
    for (int k = 0; k < NK; k++)
        #pragma unroll
        for (int c = 0; c < NC; c++) {
            float s   = __expf(sigma[k * NC + c]) + 1e-6f;
            float inv = 1.0f / s;
            a2[k][c]  = -0.5f * 1.4426950408889634f * inv * inv;
        }
    bool uni = true;
    #pragma unroll
    for (int k = 1; k < NK; k++)
        #pragma unroll
        for (int c = 0; c < NC; c++)
            uni = uni && (a2[k][c] == a2[0][c]);

    float gw[NK];
    #pragma unroll
    for (int k = 0; k < NK; k++) gw[k] = g_w[k];

    const float* xg = x_grid + b * NG * NC;
    const float* hg = h_grid + b * NG * NK * NC;
    const int tbase = blockIdx.x * T_PER_BLOCK + warp * TGT_PER_WARP;
    const float* tp = target_x + (b * NT + tbase) * NC;
    const float bb  = g_b[0];

    float acc[TGT_PER_WARP][NC];
    #pragma unroll
    for (int j = 0; j < TGT_PER_WARP; j++)
        #pragma unroll
        for (int c = 0; c < NC; c++) acc[j][c] = 0.f;

    if (uni) {
        // ======== FAST PATH ========
        const float r0 = sqrtf(-a2[0][0]);
        const float r1 = sqrtf(-a2[0][1]);
        const float r2 = sqrtf(-a2[0][2]);

        // stage: scaled coords + hsum, straight from raw inputs
        for (int r = tid; r < NG; r += TPB) {
            const float* xp = xg + r * NC;
            const float* hp = hg + r * NK * NC;
            float h0 = 0.f, h1 = 0.f, h2 = 0.f;
            #pragma unroll
            for (int k = 0; k < NK; k++) {
                h0 += gw[k] * hp[k * NC + 0];
                h1 += gw[k] * hp[k * NC + 1];
                h2 += gw[k] * hp[k * NC + 2];
            }
            sxs[r] = make_float4(xp[0] * r0, xp[1] * r1, xp[2] * r2, 0.f);
            shs[r] = make_float4(h0, h1, h2, 0.f);
        }

        // scaled targets (4 per warp)
        float tc[TGT_PER_WARP][NC];
        #pragma unroll
        for (int j = 0; j < TGT_PER_WARP; j++) {
            tc[j][0] = tp[j * NC + 0] * r0;
            tc[j][1] = tp[j * NC + 1] * r1;
            tc[j][2] = tp[j * NC + 2] * r2;
        }
        __syncthreads();

        #pragma unroll 2
        for (int i = 0; i < NG / 32; i++) {
            const int g = i * 32 + lane;
            const float4 xv = sxs[g];
            const float4 hv = shs[g];
            #pragma unroll
            for (int j = 0; j < TGT_PER_WARP; j++) {
                float d;
                d = xv.x - tc[j][0]; acc[j][0] += hv.x * ex2f(d * (-d));
                d = xv.y - tc[j][1]; acc[j][1] += hv.y * ex2f(d * (-d));
                d = xv.z - tc[j][2]; acc[j][2] += hv.z * ex2f(d * (-d));
            }
        }
    } else {
        // ======== GENERAL PATH: per-(k,c) scales ========
        float (*sx)[NG] = (float(*)[NG])smem_buf;   // rows 0..2: x, 3..17: h*gw

        for (int idx = tid; idx < NG * NC; idx += TPB) {
            int g = idx / NC, c = idx - g * NC;
            sx[c][g] = xg[idx];
        }
        for (int idx = tid; idx < NG * NK * NC; idx += TPB) {
            int g = idx / (NK * NC);
            int r = idx - g * (NK * NC);    // r = k*NC + c
            sx[NC + r][g] = hg[idx] * gw[r / NC];
        }

        float tc[TGT_PER_WARP][NC];
        #pragma unroll
        for (int j = 0; j < TGT_PER_WARP; j++)
            #pragma unroll
            for (int c = 0; c < NC; c++)
                tc[j][c] = tp[j * NC + c];
        __syncthreads();

        for (int i = 0; i < NG / 32; i++) {
            const int g = i * 32 + lane;
            const float x0 = sx[0][g], x1 = sx[1][g], x2 = sx[2][g];
            float u[TGT_PER_WARP][NC];
            #pragma unroll
            for (int j = 0; j < TGT_PER_WARP; j++) {
                u[j][0] = (x0 - tc[j][0]) * (x0 - tc[j][0]);
                u[j][1] = (x1 - tc[j][1]) * (x1 - tc[j][1]);
                u[j][2] = (x2 - tc[j][2]) * (x2 - tc[j][2]);
            }
            #pragma unroll
            for (int k = 0; k < NK; k++) {
                const float h0 = sx[NC + k * NC + 0][g];
                const float h1 = sx[NC + k * NC + 1][g];
                const float h2 = sx[NC + k * NC + 2][g];
                #pragma unroll
                for (int j = 0; j < TGT_PER_WARP; j++) {
                    acc[j][0] += h0 * ex2f(a2[k][0] * u[j][0]);
                    acc[j][1] += h1 * ex2f(a2[k][1] * u[j][1]);
                    acc[j][2] += h2 * ex2f(a2[k][2] * u[j][2]);
                }
            }
        }
    }

    // ---- reductions + store ----
    #pragma unroll
    for (int j = 0; j < TGT_PER_WARP; j++)
        #pragma unroll
        for (int c = 0; c < NC; c++)
            acc[j][c] = warp_sum(acc[j][c]);

    if (lane == 0) {
        #pragma unroll
        for (int j = 0; j < TGT_PER_WARP; j++) {
            float* o = out + (b * NT + tbase + j) * NC;
            o[0] = acc[j][0] + bb;
            o[1] = acc[j][1] + bb;
            o[2] = acc[j][2] + bb;
        }
    }
}

extern "C" void kernel_launch(void* const* d_in, const int* in_sizes, int n_in,
                              void* d_out, int out_size)
{
    const float* x_grid   = (const float*)d_in[0];  // (8, 512, 3)
    const float* h_grid   = (const float*)d_in[1];  // (8, 512, 5, 3)
    const float* target_x = (const float*)d_in[2];  // (8, 1024, 3)
    const float* sigma    = (const float*)d_in[3];  // (5, 3)
    const float* g_w      = (const float*)d_in[4];  // (1, 5)
    const float* g_b      = (const float*)d_in[5];  // (1,)
    float* out = (float*)d_out;                     // (8, 1024, 3)

    dim3 grid(NT / T_PER_BLOCK, NB);   // 32 x 8 = 256 blocks
    fused_kernel<<<grid, TPB>>>(x_grid, h_grid, target_x, sigma, g_w, g_b, out);
}